// round 4
// baseline (speedup 1.0000x reference)
#include <cuda_runtime.h>
#include <math.h>

#define BB 256
#define TT 64
#define HH 256
#define DD 8
#define NB 148   // persistent grid size; <= SM count so all CTAs co-resident

struct GruP {
    const float *Wih0, *Whh0, *bih0, *bhh0;
    const float *Wih1, *Whh1, *bih1, *bhh1;
};

// Persistent state (device globals: allocation-free scratch)
__device__ float g_h   [2*2*BB*HH];          // [s][l][b][h]  carried (post-attention) hidden
__device__ float g_hnew[2*2*BB*HH];          // [s][l][b][h]  fresh GRU hidden this step
__device__ float g_ctx [2*2*BB*HH];          // [s][o][b][h]  attention context
__device__ float g_es  [2*2*BB*HH];          // [s][l][b][g]  query projection
__device__ float g_buf [2*BB*TT*2*HH];       // [s][b][t][l][h]  hidden history
__device__ float g_eh  [2*BB*TT*2*HH];       // [s][b][t][l][g]  cached history projection
__device__ float g_out [2*TT*BB*HH];         // [s][t][b][h]  top-layer GRU outputs

__device__ unsigned int g_bar;               // rolling barrier ticket counter

__device__ __forceinline__ float sigm(float x) { return 1.0f / (1.0f + __expf(-x)); }
__device__ __forceinline__ float tanh_fast(float x) {
    float y;
    asm("tanh.approx.f32 %0, %1;" : "=f"(y) : "f"(x));
    return y;
}

// Grid-wide barrier: rolling ticket (never reset -> replay-safe), release/acquire
// via __threadfence (gpu scope -> L1 invalidate on sm_103a).
__device__ __forceinline__ void gsync() {
    __syncthreads();
    if (threadIdx.x == 0) {
        __threadfence();
        unsigned int t = atomicAdd(&g_bar, 1u);
        unsigned int target = t - (t % NB) + NB;
        volatile unsigned int* p = &g_bar;
        while ((int)(*p - target) < 0) { }
        __threadfence();
    }
    __syncthreads();
}

__global__ __launch_bounds__(256, 1) void mega(
    const float* __restrict__ recv, GruP p1, GruP p2,
    const float* __restrict__ fc_W, const float* __restrict__ fc_b,
    const float* __restrict__ attn_W, const float* __restrict__ v_W,
    const float* __restrict__ out_W, const float* __restrict__ out_b,
    float* __restrict__ out)
{
    __shared__ float sh[8 * 32 * 33];   // 33.8 KB, reused by every stage
    const int bid = blockIdx.x;
    const int tid = threadIdx.x;
    const int tx = tid & 15, ty = tid >> 4;

    // init carried hidden to zero
    for (int i = bid * 256 + tid; i < 2*2*BB*HH; i += NB * 256) g_h[i] = 0.0f;
    gsync();

    for (int step = 0; step < TT; step++) {

        // ================= Stage A: GRU layer 0 (128 tiles of 32x32) =========
        if (bid < 128) {
            const int s = bid >> 6;
            const GruP P = s ? p2 : p1;
            const int b0 = ((bid >> 3) & 7) * 32, hc0 = (bid & 7) * 32;
            float (*As)[33] = (float(*)[33])sh;
            float (*Ws)[32][33] = (float(*)[32][33])(sh + 1056);
            const float* __restrict__ hprev = g_h + (s*2 + 0) * BB * HH;
            float acc[2][2][3] = {};
            for (int k0 = 0; k0 < HH; k0 += 32) {
#pragma unroll
                for (int r = 0; r < 4; r++) {
                    int idx = tid + r*256, ar = idx >> 5, ac = idx & 31;
                    As[ar][ac] = hprev[(b0 + ar) * HH + k0 + ac];
                }
#pragma unroll
                for (int g = 0; g < 3; g++)
#pragma unroll
                    for (int r = 0; r < 4; r++) {
                        int idx = tid + r*256, wr = idx >> 5, wc = idx & 31;
                        Ws[g][wr][wc] = P.Whh0[(g*HH + hc0 + wr) * HH + k0 + wc];
                    }
                __syncthreads();
#pragma unroll
                for (int kk = 0; kk < 32; kk++) {
                    float a0 = As[2*ty + 0][kk], a1 = As[2*ty + 1][kk];
#pragma unroll
                    for (int c = 0; c < 2; c++) {
                        int h = 2*tx + c;
                        float w0 = Ws[0][h][kk], w1 = Ws[1][h][kk], w2 = Ws[2][h][kk];
                        acc[0][c][0] += a0*w0; acc[0][c][1] += a0*w1; acc[0][c][2] += a0*w2;
                        acc[1][c][0] += a1*w0; acc[1][c][1] += a1*w1; acc[1][c][2] += a1*w2;
                    }
                }
                __syncthreads();
            }
#pragma unroll
            for (int r = 0; r < 2; r++) {
                int b = b0 + 2*ty + r;
                float x0 = recv[(b*TT + step)*2 + 0];
                float x1 = recv[(b*TT + step)*2 + 1];
#pragma unroll
                for (int c = 0; c < 2; c++) {
                    int h = hc0 + 2*tx + c;
                    float ir  = P.Wih0[h*2]          * x0 + P.Wih0[h*2 + 1]          * x1 + P.bih0[h];
                    float iz  = P.Wih0[(HH + h)*2]   * x0 + P.Wih0[(HH + h)*2 + 1]   * x1 + P.bih0[HH + h];
                    float in_ = P.Wih0[(2*HH + h)*2] * x0 + P.Wih0[(2*HH + h)*2 + 1] * x1 + P.bih0[2*HH + h];
                    float hr = acc[r][c][0] + P.bhh0[h];
                    float hz = acc[r][c][1] + P.bhh0[HH + h];
                    float hn = acc[r][c][2] + P.bhh0[2*HH + h];
                    float rg = sigm(ir + hr);
                    float zg = sigm(iz + hz);
                    float n  = tanhf(in_ + rg * hn);
                    float hv = (1.0f - zg) * n + zg * hprev[b*HH + h];
                    g_hnew[((s*2 + 0)*BB + b)*HH + h] = hv;
                    g_buf[(((s*BB + b)*TT + step)*2 + 0)*HH + h] = hv;
                }
            }
        }
        gsync();

        // ================= Stage B: GRU layer 1 (128 tiles, double GEMM) =====
        if (bid < 128) {
            const int s = bid >> 6;
            const GruP P = s ? p2 : p1;
            const int b0 = ((bid >> 3) & 7) * 32, hc0 = (bid & 7) * 32;
            float (*A1s)[33] = (float(*)[33])sh;
            float (*A2s)[33] = (float(*)[33])(sh + 1056);
            float (*Wi)[32][33] = (float(*)[32][33])(sh + 2*1056);
            float (*Wh)[32][33] = (float(*)[32][33])(sh + 5*1056);
            const float* __restrict__ xin = g_hnew + (s*2 + 0) * BB * HH;
            const float* __restrict__ hp  = g_h    + (s*2 + 1) * BB * HH;
            float ai[2][2][3] = {}, ah[2][2][3] = {};
            for (int k0 = 0; k0 < HH; k0 += 32) {
#pragma unroll
                for (int r = 0; r < 4; r++) {
                    int idx = tid + r*256, ar = idx >> 5, ac = idx & 31;
                    A1s[ar][ac] = xin[(b0 + ar)*HH + k0 + ac];
                    A2s[ar][ac] = hp [(b0 + ar)*HH + k0 + ac];
                }
#pragma unroll
                for (int g = 0; g < 3; g++)
#pragma unroll
                    for (int r = 0; r < 4; r++) {
                        int idx = tid + r*256, wr = idx >> 5, wc = idx & 31;
                        Wi[g][wr][wc] = P.Wih1[(g*HH + hc0 + wr)*HH + k0 + wc];
                        Wh[g][wr][wc] = P.Whh1[(g*HH + hc0 + wr)*HH + k0 + wc];
                    }
                __syncthreads();
#pragma unroll
                for (int kk = 0; kk < 32; kk++) {
                    float x0v = A1s[2*ty + 0][kk], x1v = A1s[2*ty + 1][kk];
                    float h0v = A2s[2*ty + 0][kk], h1v = A2s[2*ty + 1][kk];
#pragma unroll
                    for (int c = 0; c < 2; c++) {
                        int h = 2*tx + c;
#pragma unroll
                        for (int g = 0; g < 3; g++) {
                            float wi = Wi[g][h][kk], wh = Wh[g][h][kk];
                            ai[0][c][g] += x0v*wi; ai[1][c][g] += x1v*wi;
                            ah[0][c][g] += h0v*wh; ah[1][c][g] += h1v*wh;
                        }
                    }
                }
                __syncthreads();
            }
#pragma unroll
            for (int r = 0; r < 2; r++) {
                int b = b0 + 2*ty + r;
#pragma unroll
                for (int c = 0; c < 2; c++) {
                    int h = hc0 + 2*tx + c;
                    float ir  = ai[r][c][0] + P.bih1[h];
                    float iz  = ai[r][c][1] + P.bih1[HH + h];
                    float in_ = ai[r][c][2] + P.bih1[2*HH + h];
                    float hr  = ah[r][c][0] + P.bhh1[h];
                    float hz  = ah[r][c][1] + P.bhh1[HH + h];
                    float hn  = ah[r][c][2] + P.bhh1[2*HH + h];
                    float rg = sigm(ir + hr);
                    float zg = sigm(iz + hz);
                    float n  = tanhf(in_ + rg * hn);
                    float hv = (1.0f - zg) * n + zg * hp[b*HH + h];
                    g_hnew[((s*2 + 1)*BB + b)*HH + h] = hv;
                    g_buf[(((s*BB + b)*TT + step)*2 + 1)*HH + h] = hv;
                    g_out[((s*TT + step)*BB + b)*HH + h] = hv;
                }
            }
        }
        gsync();

        // ================= Stage C: attention projections (256 tiles) ========
        for (int t5 = bid; t5 < 256; t5 += NB) {
            const int g0 = (t5 & 7) * 32, m0 = (t5 >> 3) * 32;
            float (*As)[33]  = (float(*)[33])sh;
            float (*W1s)[33] = (float(*)[33])(sh + 1056);
            float (*W2s)[33] = (float(*)[33])(sh + 2*1056);
            float a1[2][2] = {}, a2[2][2] = {};
            for (int k0 = 0; k0 < HH; k0 += 32) {
#pragma unroll
                for (int r = 0; r < 4; r++) {
                    int idx = tid + r*256, rr = idx >> 5, cc = idx & 31;
                    As [rr][cc] = g_hnew[(m0 + rr)*HH + k0 + cc];
                    W1s[rr][cc] = attn_W[(g0 + rr)*(2*HH) + k0 + cc];
                    W2s[rr][cc] = attn_W[(g0 + rr)*(2*HH) + HH + k0 + cc];
                }
                __syncthreads();
#pragma unroll
                for (int kk = 0; kk < 32; kk++) {
                    float v0 = As[2*ty + 0][kk], v1 = As[2*ty + 1][kk];
#pragma unroll
                    for (int c = 0; c < 2; c++) {
                        float w1 = W1s[2*tx + c][kk], w2 = W2s[2*tx + c][kk];
                        a1[0][c] += v0*w1; a1[1][c] += v1*w1;
                        a2[0][c] += v0*w2; a2[1][c] += v1*w2;
                    }
                }
                __syncthreads();
            }
#pragma unroll
            for (int r = 0; r < 2; r++) {
                int m = m0 + 2*ty + r;
                int s = m >> 9, l = (m >> 8) & 1, b = m & 255;
#pragma unroll
                for (int c = 0; c < 2; c++) {
                    int g = g0 + 2*tx + c;
                    g_es[m*HH + g] = a1[r][c];
                    g_eh[(((s*BB + b)*TT + step)*2 + l)*HH + g] = a2[r][c];
                }
            }
        }
        gsync();

        // ================= Stage D: energies + softmax + context =============
        {
            float* lgp  = sh;            // [2][128]
            float* invp = sh + 2*128;    // [2]
            const int warp = tid >> 5, lane = tid & 31;
            const int nrows = 2 * (step + 1);
            for (int u = bid; u < 512; u += NB) {
                const int b = u & 255, s = u >> 8;
                const int l = warp & 1;
                float esr[8], vw0[8], vw1[8];
                {
                    int gb = lane * 8;
                    const float* esp = g_es + ((s*2 + l)*BB + b)*HH + gb;
#pragma unroll
                    for (int q = 0; q < 8; q++) {
                        esr[q] = esp[q];
                        vw0[q] = v_W[gb + q];
                        vw1[q] = v_W[HH + gb + q];
                    }
                }
                const float* ehbase = g_eh + ((s*BB + b)*TT*2) * HH;
                for (int r = warp; r < nrows; r += 8) {
                    const float4* ehp = (const float4*)(ehbase + r*HH) + lane*2;
                    float4 ea = ehp[0], eb = ehp[1];
                    float t0 = 0.0f, t1 = 0.0f, t;
#define ESTEP(q, e) { t = tanh_fast(esr[q] + (e)); t0 += t*vw0[q]; t1 += t*vw1[q]; }
                    ESTEP(0, ea.x) ESTEP(1, ea.y) ESTEP(2, ea.z) ESTEP(3, ea.w)
                    ESTEP(4, eb.x) ESTEP(5, eb.y) ESTEP(6, eb.z) ESTEP(7, eb.w)
#undef ESTEP
#pragma unroll
                    for (int o = 16; o; o >>= 1) {
                        t0 += __shfl_xor_sync(0xffffffffu, t0, o);
                        t1 += __shfl_xor_sync(0xffffffffu, t1, o);
                    }
                    if (lane == 0) { lgp[0*128 + r] = t0; lgp[1*128 + r] = t1; }
                }
                __syncthreads();

                if (warp < 2) {
                    int o = warp;
                    float m = -1e30f;
                    for (int r = lane; r < nrows; r += 32) m = fmaxf(m, lgp[o*128 + r]);
#pragma unroll
                    for (int off = 16; off; off >>= 1) m = fmaxf(m, __shfl_xor_sync(0xffffffffu, m, off));
                    float ss = 0.0f;
                    for (int r = lane; r < nrows; r += 32) {
                        float e = __expf(lgp[o*128 + r] - m);
                        lgp[o*128 + r] = e;
                        ss += e;
                    }
#pragma unroll
                    for (int off = 16; off; off >>= 1) ss += __shfl_xor_sync(0xffffffffu, ss, off);
                    if (lane == 0) invp[o] = 1.0f / ss;
                }
                __syncthreads();

                const float* bufbase = g_buf + ((s*BB + b)*TT*2) * HH;
                float c0 = 0.0f, c1 = 0.0f;
                int r = 0;
                for (; r + 4 <= nrows; r += 4) {
                    float v0 = bufbase[(r + 0)*HH + tid];
                    float v1 = bufbase[(r + 1)*HH + tid];
                    float v2 = bufbase[(r + 2)*HH + tid];
                    float v3 = bufbase[(r + 3)*HH + tid];
                    c0 += lgp[r]*v0 + lgp[r+1]*v1 + lgp[r+2]*v2 + lgp[r+3]*v3;
                    c1 += lgp[128+r]*v0 + lgp[128+r+1]*v1 + lgp[128+r+2]*v2 + lgp[128+r+3]*v3;
                }
                for (; r < nrows; r++) {
                    float v = bufbase[r*HH + tid];
                    c0 += lgp[r]*v;
                    c1 += lgp[128 + r]*v;
                }
                float i0 = invp[0], i1 = invp[1];
                g_ctx[((s*2 + 0)*BB + b)*HH + tid] = c0 * i0;
                g_ctx[((s*2 + 1)*BB + b)*HH + tid] = c1 * i1;
                __syncthreads();
            }
        }
        gsync();

        // ================= Stage E: fc merge (256 tiles) =====================
        for (int t5 = bid; t5 < 256; t5 += NB) {
            const int n0 = (t5 & 7) * 32, m0 = (t5 >> 3) * 32;
            float (*As)[33] = (float(*)[33])sh;
            float (*Ws)[33] = (float(*)[33])(sh + 1056);
            float acc[2][2] = {};
            for (int k0 = 0; k0 < 2*HH; k0 += 32) {
                const float* Asrc = (k0 < HH) ? g_ctx : g_hnew;
                int ko = (k0 < HH) ? k0 : (k0 - HH);
#pragma unroll
                for (int r = 0; r < 4; r++) {
                    int idx = tid + r*256, rr = idx >> 5, cc = idx & 31;
                    As[rr][cc] = Asrc[(m0 + rr)*HH + ko + cc];
                    Ws[rr][cc] = fc_W[(n0 + rr)*(2*HH) + k0 + cc];
                }
                __syncthreads();
#pragma unroll
                for (int kk = 0; kk < 32; kk++) {
                    float a0 = As[2*ty + 0][kk], a1 = As[2*ty + 1][kk];
                    float w0 = Ws[2*tx + 0][kk], w1 = Ws[2*tx + 1][kk];
                    acc[0][0] += a0*w0; acc[0][1] += a0*w1;
                    acc[1][0] += a1*w0; acc[1][1] += a1*w1;
                }
                __syncthreads();
            }
#pragma unroll
            for (int r = 0; r < 2; r++) {
                int m = m0 + 2*ty + r;
#pragma unroll
                for (int c = 0; c < 2; c++) {
                    int n = n0 + 2*tx + c;
                    g_h[m*HH + n] = acc[r][c] + fc_b[n];
                }
            }
        }
        gsync();
    }

    // ================= Stage F: final readout (128 tiles) ====================
    if (bid < 128) {
        const int t = bid >> 1, half = bid & 1;
        float* w1 = sh;
        float* w2 = sh + 256;
        w1[tid] = out_W[tid];
        w2[tid] = out_W[HH + tid];
        __syncthreads();
        int t2 = (t >= TT - DD - 1) ? (TT - 1) : (t + DD);
        float ob = out_b[0];
        const float* o1b = g_out + ((0*TT + t )*BB) * HH;
        const float* o2b = g_out + ((1*TT + t2)*BB) * HH;
        const int warp = tid >> 5, lane = tid & 31;
        for (int bb = 0; bb < 16; bb++) {
            int b = half*128 + warp*16 + bb;
            const float* o1 = o1b + b*HH;
            const float* o2 = o2b + b*HH;
            float acc = 0.0f;
#pragma unroll
            for (int h = lane; h < HH; h += 32) acc += o1[h]*w1[h] + o2[h]*w2[h];
#pragma unroll
            for (int off = 16; off; off >>= 1) acc += __shfl_xor_sync(0xffffffffu, acc, off);
            if (lane == 0) out[b*TT + t] = sigm(acc + ob);
        }
    }
}

// ---------------------------------------------------------------------------
extern "C" void kernel_launch(void* const* d_in, const int* in_sizes, int n_in,
                              void* d_out, int out_size) {
    const float* recv = (const float*)d_in[0];
    GruP p1 { (const float*)d_in[1], (const float*)d_in[2], (const float*)d_in[3], (const float*)d_in[4],
              (const float*)d_in[5], (const float*)d_in[6], (const float*)d_in[7], (const float*)d_in[8] };
    GruP p2 { (const float*)d_in[9],  (const float*)d_in[10], (const float*)d_in[11], (const float*)d_in[12],
              (const float*)d_in[13], (const float*)d_in[14], (const float*)d_in[15], (const float*)d_in[16] };
    const float* fc_W   = (const float*)d_in[17];
    const float* fc_b   = (const float*)d_in[18];
    const float* attn_W = (const float*)d_in[19];
    const float* v_W    = (const float*)d_in[20];
    const float* out_W  = (const float*)d_in[21];
    const float* out_b  = (const float*)d_in[22];
    float* out = (float*)d_out;

    mega<<<NB, 256>>>(recv, p1, p2, fc_W, fc_b, attn_W, v_W, out_W, out_b, out);
}

// round 7
// speedup vs baseline: 2.0161x; 2.0161x over previous
#include <cuda_runtime.h>
#include <math.h>

#define BB 256
#define TT 64
#define HH 256
#define DD 8

struct GruP {
    const float *Wih0, *Whh0, *bih0, *bhh0;
    const float *Wih1, *Whh1, *bih1, *bhh1;
};

// Persistent state (device globals: allocation-free scratch)
__device__ float g_h   [2*2*BB*HH];          // [s][l][b][h]  carried (post-attention) hidden
__device__ float g_hnew[2*2*BB*HH];          // [s][l][b][h]  fresh GRU hidden this step
__device__ float g_ctx [2*2*BB*HH];          // [s][o][b][h]  attention context
__device__ float g_es  [2*2*BB*HH];          // [s][l][b][g]  query projection
__device__ float g_buf [2*BB*TT*2*HH];       // [s][b][t][l][h]  hidden history
__device__ float g_eh  [2*BB*TT*2*HH];       // [s][b][t][l][g]  cached history projection
__device__ float g_out [2*TT*BB*HH];         // [s][t][b][h]  top-layer GRU outputs

__device__ __forceinline__ float sigm(float x) { return 1.0f / (1.0f + __expf(-x)); }
__device__ __forceinline__ float tanh_fast(float x) {
    float y;
    asm("tanh.approx.f32 %0, %1;" : "=f"(y) : "f"(x));
    return y;
}

__global__ void k_init() {
    int i = blockIdx.x * blockDim.x + threadIdx.x;
    if (i < 2*2*BB*HH) g_h[i] = 0.0f;
}

// ---------------------------------------------------------------------------
// K1: GRU layer 0. gh = h_prev @ Whh0^T fused with gate math.
// Tile 32b x 32h x 3gates. W transposed in smem -> float2 loads.
// grid (8 h, 8 b, 2 s), 256 threads, thread = 2b x 2h x 3g micro-tile.
// ---------------------------------------------------------------------------
__global__ __launch_bounds__(256) void k1_layer0(const float* __restrict__ recv,
                                                 GruP p1, GruP p2, int step) {
    const int s = blockIdx.z;
    const GruP P = s ? p2 : p1;
    __shared__ float As[32][33];        // [b][k]
    __shared__ float Ws[3][32][34];     // [g][k][h]  (transposed, float2-aligned)
    const int tid = threadIdx.x;
    const int tx = tid & 15, ty = tid >> 4;
    const int b0 = blockIdx.y * 32, hc0 = blockIdx.x * 32;
    const float* __restrict__ hprev = g_h + s * 2 * BB * HH;
    float acc[2][2][3] = {};

    const int bb = tid >> 3, kq = tid & 7;
    for (int k0 = 0; k0 < HH; k0 += 32) {
        {
            float4 v = *(const float4*)&hprev[(b0 + bb)*HH + k0 + 4*kq];
            As[bb][4*kq+0] = v.x; As[bb][4*kq+1] = v.y;
            As[bb][4*kq+2] = v.z; As[bb][4*kq+3] = v.w;
        }
#pragma unroll
        for (int g = 0; g < 3; g++) {
            float4 v = *(const float4*)&P.Whh0[(g*HH + hc0 + bb)*HH + k0 + 4*kq];
            Ws[g][4*kq+0][bb] = v.x; Ws[g][4*kq+1][bb] = v.y;
            Ws[g][4*kq+2][bb] = v.z; Ws[g][4*kq+3][bb] = v.w;
        }
        __syncthreads();
#pragma unroll
        for (int kk = 0; kk < 32; kk++) {
            float a0 = As[2*ty + 0][kk], a1 = As[2*ty + 1][kk];
            float2 w0 = *(float2*)&Ws[0][kk][2*tx];
            float2 w1 = *(float2*)&Ws[1][kk][2*tx];
            float2 w2 = *(float2*)&Ws[2][kk][2*tx];
            acc[0][0][0] += a0*w0.x; acc[0][1][0] += a0*w0.y;
            acc[0][0][1] += a0*w1.x; acc[0][1][1] += a0*w1.y;
            acc[0][0][2] += a0*w2.x; acc[0][1][2] += a0*w2.y;
            acc[1][0][0] += a1*w0.x; acc[1][1][0] += a1*w0.y;
            acc[1][0][1] += a1*w1.x; acc[1][1][1] += a1*w1.y;
            acc[1][0][2] += a1*w2.x; acc[1][1][2] += a1*w2.y;
        }
        __syncthreads();
    }
#pragma unroll
    for (int r = 0; r < 2; r++) {
        int b = b0 + 2*ty + r;
        float x0 = recv[(b*TT + step)*2 + 0];
        float x1 = recv[(b*TT + step)*2 + 1];
#pragma unroll
        for (int c = 0; c < 2; c++) {
            int h = hc0 + 2*tx + c;
            float ir  = P.Wih0[h*2]          * x0 + P.Wih0[h*2 + 1]          * x1 + P.bih0[h];
            float iz  = P.Wih0[(HH + h)*2]   * x0 + P.Wih0[(HH + h)*2 + 1]   * x1 + P.bih0[HH + h];
            float in_ = P.Wih0[(2*HH + h)*2] * x0 + P.Wih0[(2*HH + h)*2 + 1] * x1 + P.bih0[2*HH + h];
            float hr = acc[r][c][0] + P.bhh0[h];
            float hz = acc[r][c][1] + P.bhh0[HH + h];
            float hn = acc[r][c][2] + P.bhh0[2*HH + h];
            float rg = sigm(ir + hr);
            float zg = sigm(iz + hz);
            float n  = tanhf(in_ + rg * hn);
            float hv = (1.0f - zg) * n + zg * hprev[b*HH + h];
            g_hnew[((s*2 + 0)*BB + b)*HH + h] = hv;
            g_buf[(((s*BB + b)*TT + step)*2 + 0)*HH + h] = hv;
        }
    }
}

// ---------------------------------------------------------------------------
// K2: GRU layer 1. Two fused GEMMs (x=h0 @ Wih1^T, h1 @ Whh1^T), same tiling.
// ---------------------------------------------------------------------------
__global__ __launch_bounds__(256) void k2_layer1(GruP p1, GruP p2, int step) {
    const int s = blockIdx.z;
    const GruP P = s ? p2 : p1;
    __shared__ float A1s[32][33], A2s[32][33];
    __shared__ float Wi[3][32][34], Wh[3][32][34];
    const int tid = threadIdx.x;
    const int tx = tid & 15, ty = tid >> 4;
    const int b0 = blockIdx.y * 32, hc0 = blockIdx.x * 32;
    const float* __restrict__ xin = g_hnew + (s*2 + 0) * BB * HH;
    const float* __restrict__ hp  = g_h    + (s*2 + 1) * BB * HH;
    float ai[2][2][3] = {}, ah[2][2][3] = {};

    const int bb = tid >> 3, kq = tid & 7;
    for (int k0 = 0; k0 < HH; k0 += 32) {
        {
            float4 v = *(const float4*)&xin[(b0 + bb)*HH + k0 + 4*kq];
            A1s[bb][4*kq+0] = v.x; A1s[bb][4*kq+1] = v.y;
            A1s[bb][4*kq+2] = v.z; A1s[bb][4*kq+3] = v.w;
            float4 u = *(const float4*)&hp[(b0 + bb)*HH + k0 + 4*kq];
            A2s[bb][4*kq+0] = u.x; A2s[bb][4*kq+1] = u.y;
            A2s[bb][4*kq+2] = u.z; A2s[bb][4*kq+3] = u.w;
        }
#pragma unroll
        for (int g = 0; g < 3; g++) {
            float4 v = *(const float4*)&P.Wih1[(g*HH + hc0 + bb)*HH + k0 + 4*kq];
            Wi[g][4*kq+0][bb] = v.x; Wi[g][4*kq+1][bb] = v.y;
            Wi[g][4*kq+2][bb] = v.z; Wi[g][4*kq+3][bb] = v.w;
            float4 u = *(const float4*)&P.Whh1[(g*HH + hc0 + bb)*HH + k0 + 4*kq];
            Wh[g][4*kq+0][bb] = u.x; Wh[g][4*kq+1][bb] = u.y;
            Wh[g][4*kq+2][bb] = u.z; Wh[g][4*kq+3][bb] = u.w;
        }
        __syncthreads();
#pragma unroll
        for (int kk = 0; kk < 32; kk++) {
            float x0v = A1s[2*ty + 0][kk], x1v = A1s[2*ty + 1][kk];
            float h0v = A2s[2*ty + 0][kk], h1v = A2s[2*ty + 1][kk];
#pragma unroll
            for (int g = 0; g < 3; g++) {
                float2 wi = *(float2*)&Wi[g][kk][2*tx];
                float2 wh = *(float2*)&Wh[g][kk][2*tx];
                ai[0][0][g] += x0v*wi.x; ai[0][1][g] += x0v*wi.y;
                ai[1][0][g] += x1v*wi.x; ai[1][1][g] += x1v*wi.y;
                ah[0][0][g] += h0v*wh.x; ah[0][1][g] += h0v*wh.y;
                ah[1][0][g] += h1v*wh.x; ah[1][1][g] += h1v*wh.y;
            }
        }
        __syncthreads();
    }
#pragma unroll
    for (int r = 0; r < 2; r++) {
        int b = b0 + 2*ty + r;
#pragma unroll
        for (int c = 0; c < 2; c++) {
            int h = hc0 + 2*tx + c;
            float ir  = ai[r][c][0] + P.bih1[h];
            float iz  = ai[r][c][1] + P.bih1[HH + h];
            float in_ = ai[r][c][2] + P.bih1[2*HH + h];
            float hr  = ah[r][c][0] + P.bhh1[h];
            float hz  = ah[r][c][1] + P.bhh1[HH + h];
            float hn  = ah[r][c][2] + P.bhh1[2*HH + h];
            float rg = sigm(ir + hr);
            float zg = sigm(iz + hz);
            float n  = tanhf(in_ + rg * hn);
            float hv = (1.0f - zg) * n + zg * hp[b*HH + h];
            g_hnew[((s*2 + 1)*BB + b)*HH + h] = hv;
            g_buf[(((s*BB + b)*TT + step)*2 + 1)*HH + h] = hv;
            g_out[((s*TT + step)*BB + b)*HH + h] = hv;
        }
    }
}

// ---------------------------------------------------------------------------
// K3: attention projections. Single GEMM M=1024, N=512 (es||eh), K=256.
// Tile 64m x 64n, BK=32, 4x4 register micro-tile. grid (8 n, 16 m).
// ---------------------------------------------------------------------------
__global__ __launch_bounds__(256) void k3_proj(const float* __restrict__ attn_W, int step) {
    __shared__ float As[64][36];   // [m][k], float4-aligned stride
    __shared__ float Bs[32][68];   // [k][n], float4-aligned stride
    const int tid = threadIdx.x;
    const int tx = tid & 15, ty = tid >> 4;
    const int n0 = blockIdx.x * 64, m0 = blockIdx.y * 64;
    // B source: n<256 -> attn_W[n][k] ; n>=256 -> attn_W[n-256][256+k]
    const float* __restrict__ bsrc = (n0 < 256) ? (attn_W + n0*(2*HH))
                                                : (attn_W + (n0 - 256)*(2*HH) + HH);
    float acc[4][4] = {};

    for (int k0 = 0; k0 < HH; k0 += 32) {
#pragma unroll
        for (int i = 0; i < 2; i++) {
            int q = tid + i*256;
            int mm = q >> 3, kq = q & 7;
            float4 v = *(const float4*)&g_hnew[(m0 + mm)*HH + k0 + 4*kq];
            *(float4*)&As[mm][4*kq] = v;
            float4 u = *(const float4*)&bsrc[mm*(2*HH) + k0 + 4*kq];  // mm = nn here
            Bs[4*kq+0][mm] = u.x; Bs[4*kq+1][mm] = u.y;
            Bs[4*kq+2][mm] = u.z; Bs[4*kq+3][mm] = u.w;
        }
        __syncthreads();
#pragma unroll
        for (int kk = 0; kk < 32; kk++) {
            float4 bv = *(float4*)&Bs[kk][4*tx];
            float a0 = As[4*ty + 0][kk];
            float a1 = As[4*ty + 1][kk];
            float a2 = As[4*ty + 2][kk];
            float a3 = As[4*ty + 3][kk];
            acc[0][0] += a0*bv.x; acc[0][1] += a0*bv.y; acc[0][2] += a0*bv.z; acc[0][3] += a0*bv.w;
            acc[1][0] += a1*bv.x; acc[1][1] += a1*bv.y; acc[1][2] += a1*bv.z; acc[1][3] += a1*bv.w;
            acc[2][0] += a2*bv.x; acc[2][1] += a2*bv.y; acc[2][2] += a2*bv.z; acc[2][3] += a2*bv.w;
            acc[3][0] += a3*bv.x; acc[3][1] += a3*bv.y; acc[3][2] += a3*bv.z; acc[3][3] += a3*bv.w;
        }
        __syncthreads();
    }
#pragma unroll
    for (int r = 0; r < 4; r++) {
        int m = m0 + 4*ty + r;
        int s = m >> 9, l = (m >> 8) & 1, b = m & 255;
        if (n0 < 256) {
#pragma unroll
            for (int c = 0; c < 4; c++) g_es[m*HH + n0 + 4*tx + c] = acc[r][c];
        } else {
            float* dst = g_eh + (((s*BB + b)*TT + step)*2 + l)*HH + (n0 - 256) + 4*tx;
#pragma unroll
            for (int c = 0; c < 4; c++) dst[c] = acc[r][c];
        }
    }
}

// ---------------------------------------------------------------------------
// K4: attention energies (tanh.approx) + softmax + context. Block per (b, s).
// ---------------------------------------------------------------------------
__global__ __launch_bounds__(256) void k4_attend(const float* __restrict__ v_W, int step) {
    const int b = blockIdx.x, s = blockIdx.y;
    const int tid = threadIdx.x, warp = tid >> 5, lane = tid & 31;
    __shared__ float lg[2][2*TT];
    __shared__ float inv[2];
    const int nrows = 2 * (step + 1);

    const int l = warp & 1;
    float esr[8], vw0[8], vw1[8];
    {
        int gb = lane * 8;
        const float* esp = g_es + ((s*2 + l)*BB + b)*HH + gb;
#pragma unroll
        for (int u = 0; u < 8; u++) {
            esr[u] = esp[u];
            vw0[u] = v_W[gb + u];
            vw1[u] = v_W[HH + gb + u];
        }
    }
    const float* ehbase = g_eh + ((s*BB + b)*TT*2) * HH;
    for (int r = warp; r < nrows; r += 8) {
        const float4* ehp = (const float4*)(ehbase + r*HH) + lane*2;
        float4 ea = ehp[0], eb = ehp[1];
        float t0 = 0.0f, t1 = 0.0f, t;
#define ESTEP(u, e) { t = tanh_fast(esr[u] + (e)); t0 += t*vw0[u]; t1 += t*vw1[u]; }
        ESTEP(0, ea.x) ESTEP(1, ea.y) ESTEP(2, ea.z) ESTEP(3, ea.w)
        ESTEP(4, eb.x) ESTEP(5, eb.y) ESTEP(6, eb.z) ESTEP(7, eb.w)
#undef ESTEP
#pragma unroll
        for (int o = 16; o; o >>= 1) {
            t0 += __shfl_xor_sync(0xffffffffu, t0, o);
            t1 += __shfl_xor_sync(0xffffffffu, t1, o);
        }
        if (lane == 0) { lg[0][r] = t0; lg[1][r] = t1; }
    }
    __syncthreads();

    if (warp < 2) {
        int o = warp;
        float m = -1e30f;
        for (int r = lane; r < nrows; r += 32) m = fmaxf(m, lg[o][r]);
#pragma unroll
        for (int off = 16; off; off >>= 1) m = fmaxf(m, __shfl_xor_sync(0xffffffffu, m, off));
        float ss = 0.0f;
        for (int r = lane; r < nrows; r += 32) {
            float e = __expf(lg[o][r] - m);
            lg[o][r] = e;
            ss += e;
        }
#pragma unroll
        for (int off = 16; off; off >>= 1) ss += __shfl_xor_sync(0xffffffffu, ss, off);
        if (lane == 0) inv[o] = 1.0f / ss;
    }
    __syncthreads();

    const float* bufbase = g_buf + ((s*BB + b)*TT*2) * HH;
    float c0 = 0.0f, c1 = 0.0f;
    int r = 0;
    for (; r + 4 <= nrows; r += 4) {
        float v0 = bufbase[(r + 0)*HH + tid];
        float v1 = bufbase[(r + 1)*HH + tid];
        float v2 = bufbase[(r + 2)*HH + tid];
        float v3 = bufbase[(r + 3)*HH + tid];
        c0 += lg[0][r]*v0 + lg[0][r+1]*v1 + lg[0][r+2]*v2 + lg[0][r+3]*v3;
        c1 += lg[1][r]*v0 + lg[1][r+1]*v1 + lg[1][r+2]*v2 + lg[1][r+3]*v3;
    }
    for (; r < nrows; r++) {
        float v = bufbase[r*HH + tid];
        c0 += lg[0][r]*v;
        c1 += lg[1][r]*v;
    }
    g_ctx[((s*2 + 0)*BB + b)*HH + tid] = c0 * inv[0];
    g_ctx[((s*2 + 1)*BB + b)*HH + tid] = c1 * inv[1];
}

// ---------------------------------------------------------------------------
// K5: fc merge. GEMM M=1024 (rows = [s][o][b]), N=256, K=512 (A=[ctx|hnew]).
// Tile 64m x 32n, BK=32, 4x2 micro-tile. grid (8 n, 16 m).
// ---------------------------------------------------------------------------
__global__ __launch_bounds__(256) void k5_fc(const float* __restrict__ fc_W,
                                             const float* __restrict__ fc_b) {
    __shared__ float As[64][36];
    __shared__ float Bs[32][34];
    const int tid = threadIdx.x;
    const int tx = tid & 15, ty = tid >> 4;
    const int n0 = blockIdx.x * 32, m0 = blockIdx.y * 64;
    float acc[4][2] = {};

    for (int k0 = 0; k0 < 2*HH; k0 += 32) {
        const float* Asrc = (k0 < HH) ? g_ctx : g_hnew;
        const int ko = (k0 < HH) ? k0 : (k0 - HH);
#pragma unroll
        for (int i = 0; i < 2; i++) {
            int q = tid + i*256;
            int mm = q >> 3, kq = q & 7;
            float4 v = *(const float4*)&Asrc[(m0 + mm)*HH + ko + 4*kq];
            *(float4*)&As[mm][4*kq] = v;
        }
        {
            int nn = tid >> 3, kq = tid & 7;
            float4 u = *(const float4*)&fc_W[(n0 + nn)*(2*HH) + k0 + 4*kq];
            Bs[4*kq+0][nn] = u.x; Bs[4*kq+1][nn] = u.y;
            Bs[4*kq+2][nn] = u.z; Bs[4*kq+3][nn] = u.w;
        }
        __syncthreads();
#pragma unroll
        for (int kk = 0; kk < 32; kk++) {
            float2 bv = *(float2*)&Bs[kk][2*tx];
            float a0 = As[4*ty + 0][kk];
            float a1 = As[4*ty + 1][kk];
            float a2 = As[4*ty + 2][kk];
            float a3 = As[4*ty + 3][kk];
            acc[0][0] += a0*bv.x; acc[0][1] += a0*bv.y;
            acc[1][0] += a1*bv.x; acc[1][1] += a1*bv.y;
            acc[2][0] += a2*bv.x; acc[2][1] += a2*bv.y;
            acc[3][0] += a3*bv.x; acc[3][1] += a3*bv.y;
        }
        __syncthreads();
    }
#pragma unroll
    for (int r = 0; r < 4; r++) {
        int m = m0 + 4*ty + r;
#pragma unroll
        for (int c = 0; c < 2; c++) {
            int n = n0 + 2*tx + c;
            g_h[m*HH + n] = acc[r][c] + fc_b[n];
        }
    }
}

// ---------------------------------------------------------------------------
// K6: final readout: sigmoid([out1 | delayed out2] @ out_W^T + out_b)
// ---------------------------------------------------------------------------
__global__ __launch_bounds__(256) void k6_out(const float* __restrict__ out_W,
                                              const float* __restrict__ out_b,
                                              float* __restrict__ out) {
    const int t = blockIdx.x;
    const int tid = threadIdx.x, warp = tid >> 5, lane = tid & 31;
    __shared__ float w1[HH], w2[HH];
    w1[tid] = out_W[tid];
    w2[tid] = out_W[HH + tid];
    __syncthreads();
    int t2 = (t >= TT - DD - 1) ? (TT - 1) : (t + DD);
    float ob = out_b[0];
    const float* o1b = g_out + ((0*TT + t )*BB) * HH;
    const float* o2b = g_out + ((1*TT + t2)*BB) * HH;
    for (int bb = 0; bb < 32; bb++) {
        int b = warp*32 + bb;
        const float* o1 = o1b + b*HH;
        const float* o2 = o2b + b*HH;
        float acc = 0.0f;
#pragma unroll
        for (int h = lane; h < HH; h += 32) acc += o1[h]*w1[h] + o2[h]*w2[h];
#pragma unroll
        for (int off = 16; off; off >>= 1) acc += __shfl_xor_sync(0xffffffffu, acc, off);
        if (lane == 0) out[b*TT + t] = sigm(acc + ob);
    }
}

// ---------------------------------------------------------------------------
extern "C" void kernel_launch(void* const* d_in, const int* in_sizes, int n_in,
                              void* d_out, int out_size) {
    const float* recv = (const float*)d_in[0];
    GruP p1 { (const float*)d_in[1], (const float*)d_in[2], (const float*)d_in[3], (const float*)d_in[4],
              (const float*)d_in[5], (const float*)d_in[6], (const float*)d_in[7], (const float*)d_in[8] };
    GruP p2 { (const float*)d_in[9],  (const float*)d_in[10], (const float*)d_in[11], (const float*)d_in[12],
              (const float*)d_in[13], (const float*)d_in[14], (const float*)d_in[15], (const float*)d_in[16] };
    const float* fc_W   = (const float*)d_in[17];
    const float* fc_b   = (const float*)d_in[18];
    const float* attn_W = (const float*)d_in[19];
    const float* v_W    = (const float*)d_in[20];
    const float* out_W  = (const float*)d_in[21];
    const float* out_b  = (const float*)d_in[22];
    float* out = (float*)d_out;

    k_init<<<(2*2*BB*HH + 255)/256, 256>>>();

    for (int i = 0; i < TT; i++) {
        k1_layer0<<<dim3(8, 8, 2),  256>>>(recv, p1, p2, i);
        k2_layer1<<<dim3(8, 8, 2),  256>>>(p1, p2, i);
        k3_proj  <<<dim3(8, 16),    256>>>(attn_W, i);
        k4_attend<<<dim3(BB, 2),    256>>>(v_W, i);
        k5_fc    <<<dim3(8, 16),    256>>>(fc_W, fc_b);
    }
    k6_out<<<TT, 256>>>(out_W, out_b, out);
}